// round 13
// baseline (speedup 1.0000x reference)
#include <cuda_runtime.h>
#include <cuda_fp16.h>
#include <math.h>

#define TB 32          // batch elements per CTA (lane == element)
#define NTHREADS 512   // 16 warps

// ---------------- shared memory layout (float-slot offsets) ----------------
// SIG2H [0, 16384)       half[k=256][e=32][t=4]          (16384 slots)
// SIGT  [16384, 37504)   float 640 x 32, stride 33       (21120 slots)
// MAGH  [16384, 24640)   half[c=129][e=32][t=4]          (8256 slots, over dead SIGT)
// FPART [24640, 28736)   float 16 x 32 x 8
// Y1H   [0, 8192)        half[c=128][e][4]               (over dead SIG2H)
// Y2    [8192, 12288)    float[c=64][e][2]
// Y3    [12288, 14336)   float[c=64][e]
// Y4    [14336, 18432)   float[q=32][e][4]               (MAG dead by then)
// PARTS [18432, 18944)
#define SIG2H 0
#define SIGT  16384
#define MAGH  16384
#define FPART 24640
#define Y1H   0
#define Y2    8192
#define Y3    12288
#define Y4    14336
#define PARTS 18432
#define SMEM_FLOATS 37504

// ---------------- packed-weight scratch (__device__ globals, filled by prep) ----
__device__ float g_stft_wp[256 * 264];      // [k][2f interleaved (re,im)], row padded to 264
__device__ float g_e1_wp[32 * 129 * 12];    // [g(4ch)][c][j*4 + ch_in_quad]
__device__ float g_e2_wp[16 * 128 * 12];    // [g][c][j*4 + m]
__device__ float g_e3_wp[16 * 64 * 8];      // [g][c][ch0:(w1,w2), ch1:(w1,w2), ...]
__device__ float g_e4_wp[32 * 64 * 4];      // [g][c][center tap for 4 ch]

typedef unsigned long long f32x2;

static __device__ __forceinline__ f32x2 b2(float v) {
    f32x2 r; unsigned u = __float_as_uint(v);
    asm("mov.b64 %0, {%1,%2};" : "=l"(r) : "r"(u), "r"(u));
    return r;
}
static __device__ __forceinline__ void up2(f32x2 v, float& lo, float& hi) {
    unsigned a, b;
    asm("mov.b64 {%0,%1}, %2;" : "=r"(a), "=r"(b) : "l"(v));
    lo = __uint_as_float(a); hi = __uint_as_float(b);
}
static __device__ __forceinline__ f32x2 ffma2(f32x2 a, f32x2 b, f32x2 c) {
    f32x2 d;
    asm("fma.rn.f32x2 %0, %1, %2, %3;" : "=l"(d) : "l"(a), "l"(b), "l"(c));
    return d;
}
static __device__ __forceinline__ float sigmoidf_(float x) {
    return 1.0f / (1.0f + __expf(-x));
}
// pack 4 floats -> uint2 of 4 halves
static __device__ __forceinline__ uint2 h4pack(float a, float b, float c, float d) {
    __half2 h01 = __floats2half2_rn(a, b);
    __half2 h23 = __floats2half2_rn(c, d);
    uint2 r;
    r.x = *(unsigned*)&h01;
    r.y = *(unsigned*)&h23;
    return r;
}
// unpack uint2 of 4 halves -> 4 floats
static __device__ __forceinline__ void h4unpack(uint2 v, float& a, float& b, float& c, float& d) {
    float2 f01 = __half22float2(*(__half2*)&v.x);
    float2 f23 = __half22float2(*(__half2*)&v.y);
    a = f01.x; b = f01.y; c = f23.x; d = f23.y;
}

// ---------------- weight prep (runs each launch; ~5us) ----------------
__global__ void vad_prep(const float* __restrict__ stft_w,
                         const float* __restrict__ e1_w,
                         const float* __restrict__ e2_w,
                         const float* __restrict__ e3_w,
                         const float* __restrict__ e4_w)
{
    int t0 = blockIdx.x * blockDim.x + threadIdx.x;
    int stride = gridDim.x * blockDim.x;
    for (int i = t0; i < 256 * 129; i += stride) {
        int k = i / 129, f = i - k * 129;
        g_stft_wp[k * 264 + 2 * f]     = stft_w[f * 256 + k];
        g_stft_wp[k * 264 + 2 * f + 1] = stft_w[(f + 129) * 256 + k];
    }
    for (int i = t0; i < 32 * 129 * 12; i += stride) {
        int g = i / (129 * 12), r = i - g * 129 * 12, c = r / 12, jm = r - c * 12;
        int j = jm >> 2, m = jm & 3;
        g_e1_wp[i] = e1_w[(4 * g + m) * 387 + c * 3 + j];
    }
    for (int i = t0; i < 16 * 128 * 12; i += stride) {
        int g = i / (128 * 12), r = i - g * 128 * 12, c = r / 12, jm = r - c * 12;
        int j = jm >> 2, m = jm & 3;
        g_e2_wp[i] = e2_w[(4 * g + m) * 384 + c * 3 + j];
    }
    for (int i = t0; i < 16 * 64 * 8; i += stride) {
        int g = i / (64 * 8), r = i - g * 64 * 8, c = r / 8, m2 = r - c * 8;
        int m = m2 >> 1, j = 1 + (m2 & 1);
        g_e3_wp[i] = e3_w[(4 * g + m) * 192 + c * 3 + j];
    }
    for (int i = t0; i < 32 * 64 * 4; i += stride) {
        int g = i / (64 * 4), r = i - g * 64 * 4, c = r / 4, m = r - c * 4;
        g_e4_wp[i] = e4_w[(4 * g + m) * 192 + c * 3 + 1];
    }
}

// ---------------- main fused kernel ----------------
__global__ void __launch_bounds__(NTHREADS, 1)
vad_fused(const float* __restrict__ data,
          const float* __restrict__ e1_b, const float* __restrict__ e2_b,
          const float* __restrict__ e3_b, const float* __restrict__ e4_b,
          const float* __restrict__ w_ih,
          const float* __restrict__ b_ih, const float* __restrict__ b_hh,
          const float* __restrict__ dec_w, const float* __restrict__ dec_b,
          float* __restrict__ out)
{
    extern __shared__ float sm[];
    const int tid  = threadIdx.x;
    const int wid  = tid >> 5;
    const int lane = tid & 31;
    const long long e0 = (long long)blockIdx.x * TB;
    const float* __restrict__ dbase = data + e0 * 512;

    // -------- phase A: padded signal, transposed (coalesced global reads) --------
    float* sigt = sm + SIGT;  // 640 x 32, stride 33
    for (int idx = tid; idx < 64 * TB; idx += NTHREADS) {
        int p = idx >> 5, e = idx & 31;
        sigt[p * 33 + e] = 0.0f;
    }
    for (int idx = tid; idx < 512 * TB; idx += NTHREADS) {
        int e = idx >> 9, j = idx & 511;
        sigt[(64 + j) * 33 + e] = dbase[idx];
    }
    for (int idx = tid; idx < 64 * TB; idx += NTHREADS) {
        int e = idx >> 6, j = idx & 63;
        sigt[(576 + j) * 33 + e] = dbase[e * 512 + 510 - j];
    }
    __syncthreads();

    // -------- phase B: frame-quad fp16 layout sig2[k][e][t0..t3] --------
    {
        uint2* s2 = (uint2*)(sm + SIG2H);
        for (int i = tid; i < 256 * 32; i += NTHREADS) {
            int k = i >> 5, e = i & 31;
            s2[k * 32 + e] = h4pack(sigt[k * 33 + e],
                                    sigt[(128 + k) * 33 + e],
                                    sigt[(256 + k) * 33 + e],
                                    sigt[(384 + k) * 33 + e]);
        }
    }
    __syncthreads();

    // -------- phase C: STFT + magnitude (f32x2 (re,im) pairs, 8 pairs/warp) --------
    {
        f32x2 acc[8][4];
        #pragma unroll
        for (int f = 0; f < 8; ++f)
            #pragma unroll
            for (int t = 0; t < 4; ++t) acc[f][t] = 0ull;

        const ulonglong2* __restrict__ wps = (const ulonglong2*)g_stft_wp;  // 66 per row
        const uint2* __restrict__ s2 = (const uint2*)(sm + SIG2H);

        #pragma unroll 2
        for (int k = 0; k < 256; ++k) {
            float sx, sy, sz, sw;
            h4unpack(s2[k * 32 + lane], sx, sy, sz, sw);
            f32x2 S0 = b2(sx), S1 = b2(sy), S2 = b2(sz), S3 = b2(sw);
            ulonglong2 w0 = wps[k * 66 + wid * 4 + 0];
            ulonglong2 w1 = wps[k * 66 + wid * 4 + 1];
            ulonglong2 w2 = wps[k * 66 + wid * 4 + 2];
            ulonglong2 w3 = wps[k * 66 + wid * 4 + 3];
            f32x2 W[8] = {w0.x, w0.y, w1.x, w1.y, w2.x, w2.y, w3.x, w3.y};
            #pragma unroll
            for (int f = 0; f < 8; ++f) {
                acc[f][0] = ffma2(W[f], S0, acc[f][0]);
                acc[f][1] = ffma2(W[f], S1, acc[f][1]);
                acc[f][2] = ffma2(W[f], S2, acc[f][2]);
                acc[f][3] = ffma2(W[f], S3, acc[f][3]);
            }
        }
        #pragma unroll
        for (int f = 0; f < 8; ++f) {
            float m[4];
            #pragma unroll
            for (int t = 0; t < 4; ++t) {
                float re, im; up2(acc[f][t], re, im);
                m[t] = sqrtf(re * re + im * im);
            }
            ((uint2*)(sm + MAGH))[(8 * wid + f) * 32 + lane] = h4pack(m[0], m[1], m[2], m[3]);
        }

        // filter 128: each warp takes a k-slice of 16, partials to smem (fp32)
        f32x2 r0 = 0ull, r1 = 0ull, r2 = 0ull, r3 = 0ull;
        int kb = wid * 16;
        #pragma unroll
        for (int k = kb; k < kb + 16; ++k) {
            float sx, sy, sz, sw;
            h4unpack(s2[k * 32 + lane], sx, sy, sz, sw);
            f32x2 W = *(const f32x2*)(g_stft_wp + k * 264 + 256);
            r0 = ffma2(W, b2(sx), r0);
            r1 = ffma2(W, b2(sy), r1);
            r2 = ffma2(W, b2(sz), r2);
            r3 = ffma2(W, b2(sw), r3);
        }
        float* fp = sm + FPART + (wid * 32 + lane) * 8;
        float lo, hi;
        up2(r0, lo, hi); fp[0] = lo; fp[1] = hi;
        up2(r1, lo, hi); fp[2] = lo; fp[3] = hi;
        up2(r2, lo, hi); fp[4] = lo; fp[5] = hi;
        up2(r3, lo, hi); fp[6] = lo; fp[7] = hi;
    }
    __syncthreads();
    if (tid < 128) {
        int e = tid & 31, t = tid >> 5;
        float re = 0.f, im = 0.f;
        #pragma unroll
        for (int w = 0; w < 16; ++w) {
            re += sm[FPART + (w * 32 + e) * 8 + 2 * t];
            im += sm[FPART + (w * 32 + e) * 8 + 2 * t + 1];
        }
        ((__half*)(sm + MAGH))[(128 * 32 + e) * 4 + t] = __float2half_rn(sqrtf(re * re + im * im));
    }
    __syncthreads();

    // -------- e1: conv(129->128, k3, s1, p1), channel-pair packed, fp16 mag in --------
    {
        const uint2* __restrict__ mg = (const uint2*)(sm + MAGH);
        #pragma unroll
        for (int p = 0; p < 2; ++p) {
            int g = wid * 2 + p;                       // channel quad 4g..4g+3
            ulonglong2 bb = *(const ulonglong2*)(e1_b + 4 * g);
            f32x2 a[2][4];
            #pragma unroll
            for (int t = 0; t < 4; ++t) { a[0][t] = bb.x; a[1][t] = bb.y; }
            const ulonglong2* __restrict__ wq = (const ulonglong2*)g_e1_wp + (long)g * 129 * 3;
            #pragma unroll 2
            for (int c = 0; c < 129; ++c) {
                float mx, my, mz, mw;
                h4unpack(mg[c * 32 + lane], mx, my, mz, mw);
                f32x2 M0 = b2(mx), M1 = b2(my), M2 = b2(mz), M3 = b2(mw);
                ulonglong2 W0 = wq[c * 3 + 0];
                ulonglong2 W1 = wq[c * 3 + 1];
                ulonglong2 W2 = wq[c * 3 + 2];
                a[0][0] = ffma2(W1.x, M0, ffma2(W2.x, M1, a[0][0]));
                a[0][1] = ffma2(W0.x, M0, ffma2(W1.x, M1, ffma2(W2.x, M2, a[0][1])));
                a[0][2] = ffma2(W0.x, M1, ffma2(W1.x, M2, ffma2(W2.x, M3, a[0][2])));
                a[0][3] = ffma2(W0.x, M2, ffma2(W1.x, M3, a[0][3]));
                a[1][0] = ffma2(W1.y, M0, ffma2(W2.y, M1, a[1][0]));
                a[1][1] = ffma2(W0.y, M0, ffma2(W1.y, M1, ffma2(W2.y, M2, a[1][1])));
                a[1][2] = ffma2(W0.y, M1, ffma2(W1.y, M2, ffma2(W2.y, M3, a[1][2])));
                a[1][3] = ffma2(W0.y, M2, ffma2(W1.y, M3, a[1][3]));
            }
            #pragma unroll
            for (int P = 0; P < 2; ++P) {
                int chA = 4 * g + 2 * P;
                float va[4], vb[4];
                #pragma unroll
                for (int t = 0; t < 4; ++t) {
                    float lo, hi; up2(a[P][t], lo, hi);
                    va[t] = fmaxf(lo, 0.f);
                    vb[t] = fmaxf(hi, 0.f);
                }
                ((uint2*)(sm + Y1H))[chA * 32 + lane]       = h4pack(va[0], va[1], va[2], va[3]);
                ((uint2*)(sm + Y1H))[(chA + 1) * 32 + lane] = h4pack(vb[0], vb[1], vb[2], vb[3]);
            }
        }
    }
    __syncthreads();

    // -------- e2: conv(128->64, k3, s2, p1), len 4 -> 2, fp16 y1 in --------
    {
        int g = wid;                                   // channels 4g..4g+3
        ulonglong2 bb = *(const ulonglong2*)(e2_b + 4 * g);
        f32x2 a[2][2];
        a[0][0] = bb.x; a[0][1] = bb.x;
        a[1][0] = bb.y; a[1][1] = bb.y;
        const ulonglong2* __restrict__ wq = (const ulonglong2*)g_e2_wp + (long)g * 128 * 3;
        const uint2* __restrict__ y1p = (const uint2*)(sm + Y1H);
        #pragma unroll 2
        for (int c = 0; c < 128; ++c) {
            float vx, vy, vz, vw;
            h4unpack(y1p[c * 32 + lane], vx, vy, vz, vw);
            f32x2 V0 = b2(vx), V1 = b2(vy), V2 = b2(vz), V3 = b2(vw);
            ulonglong2 W0 = wq[c * 3 + 0];
            ulonglong2 W1 = wq[c * 3 + 1];
            ulonglong2 W2 = wq[c * 3 + 2];
            a[0][0] = ffma2(W1.x, V0, ffma2(W2.x, V1, a[0][0]));
            a[0][1] = ffma2(W0.x, V1, ffma2(W1.x, V2, ffma2(W2.x, V3, a[0][1])));
            a[1][0] = ffma2(W1.y, V0, ffma2(W2.y, V1, a[1][0]));
            a[1][1] = ffma2(W0.y, V1, ffma2(W1.y, V2, ffma2(W2.y, V3, a[1][1])));
        }
        #pragma unroll
        for (int P = 0; P < 2; ++P) {
            int chA = 4 * g + 2 * P;
            float l0, h0, l1, h1;
            up2(a[P][0], l0, h0); up2(a[P][1], l1, h1);
            ((float2*)(sm + Y2))[chA * 32 + lane]       = make_float2(fmaxf(l0, 0.f), fmaxf(l1, 0.f));
            ((float2*)(sm + Y2))[(chA + 1) * 32 + lane] = make_float2(fmaxf(h0, 0.f), fmaxf(h1, 0.f));
        }
    }
    __syncthreads();

    // -------- e3: conv(64->64, k3, s2, p1), len 2 -> 1 (tap-pair packed) --------
    {
        int g = wid;                                   // channels 4g..4g+3
        f32x2 acc[4] = {0ull, 0ull, 0ull, 0ull};
        const ulonglong2* __restrict__ wq = (const ulonglong2*)g_e3_wp + (long)g * 64 * 2;
        #pragma unroll 2
        for (int c = 0; c < 64; ++c) {
            f32x2 v01 = *(const f32x2*)(sm + Y2 + (c * 32 + lane) * 2);
            ulonglong2 L0 = wq[c * 2], L1 = wq[c * 2 + 1];
            acc[0] = ffma2(L0.x, v01, acc[0]);
            acc[1] = ffma2(L0.y, v01, acc[1]);
            acc[2] = ffma2(L1.x, v01, acc[2]);
            acc[3] = ffma2(L1.y, v01, acc[3]);
        }
        #pragma unroll
        for (int m = 0; m < 4; ++m) {
            float lo, hi; up2(acc[m], lo, hi);
            sm[Y3 + (4 * g + m) * 32 + lane] = fmaxf(lo + hi + e3_b[4 * g + m], 0.f);
        }
    }
    __syncthreads();

    // -------- e4: conv(64->128, k3, s1, p1), len 1 (center tap only) --------
    {
        int q0 = wid * 2, q1 = wid * 2 + 1;            // channel quads; 8 channels/warp
        ulonglong2 bA = *(const ulonglong2*)(e4_b + 8 * wid);
        ulonglong2 bB = *(const ulonglong2*)(e4_b + 8 * wid + 4);
        f32x2 aA0 = bA.x, aA1 = bA.y, aB0 = bB.x, aB1 = bB.y;
        const ulonglong2* __restrict__ wq = (const ulonglong2*)g_e4_wp;
        #pragma unroll 2
        for (int c = 0; c < 64; ++c) {
            f32x2 V = b2(sm[Y3 + c * 32 + lane]);
            ulonglong2 WA = wq[q0 * 64 + c];
            ulonglong2 WB = wq[q1 * 64 + c];
            aA0 = ffma2(WA.x, V, aA0); aA1 = ffma2(WA.y, V, aA1);
            aB0 = ffma2(WB.x, V, aB0); aB1 = ffma2(WB.y, V, aB1);
        }
        float l0, h0, l1, h1;
        up2(aA0, l0, h0); up2(aA1, l1, h1);
        ((float4*)(sm + Y4))[q0 * 32 + lane] =
            make_float4(fmaxf(l0, 0.f), fmaxf(h0, 0.f), fmaxf(l1, 0.f), fmaxf(h1, 0.f));
        up2(aB0, l0, h0); up2(aB1, l1, h1);
        ((float4*)(sm + Y4))[q1 * 32 + lane] =
            make_float4(fmaxf(l0, 0.f), fmaxf(h0, 0.f), fmaxf(l1, 0.f), fmaxf(h1, 0.f));
    }
    __syncthreads();

    // -------- LSTM cell (h0=c0=0 => gates i,g,o), single pass over y4 --------
    {
        float psum = 0.f;
        const ulonglong2* __restrict__ W = (const ulonglong2*)w_ih;  // 32 ull2 per row
        const ulonglong2* __restrict__ y4p = (const ulonglong2*)(sm + Y4);
        const int ch0 = wid * 8;
        f32x2 ai[8], ag[8], ao[8];
        #pragma unroll
        for (int i = 0; i < 8; ++i) { ai[i] = 0ull; ag[i] = 0ull; ao[i] = 0ull; }
        #pragma unroll 2
        for (int c4 = 0; c4 < 32; ++c4) {
            ulonglong2 V = y4p[c4 * 32 + lane];
            #pragma unroll
            for (int i = 0; i < 8; ++i) {
                int ch = ch0 + i;
                ulonglong2 wi = W[(ch)       * 32 + c4];
                ulonglong2 wg = W[(ch + 256) * 32 + c4];
                ulonglong2 wo = W[(ch + 384) * 32 + c4];
                ai[i] = ffma2(wi.x, V.x, ai[i]); ai[i] = ffma2(wi.y, V.y, ai[i]);
                ag[i] = ffma2(wg.x, V.x, ag[i]); ag[i] = ffma2(wg.y, V.y, ag[i]);
                ao[i] = ffma2(wo.x, V.x, ao[i]); ao[i] = ffma2(wo.y, V.y, ao[i]);
            }
        }
        #pragma unroll
        for (int i = 0; i < 8; ++i) {
            int ch = ch0 + i;
            float lo, hi;
            up2(ai[i], lo, hi); float gi = lo + hi + b_ih[ch]       + b_hh[ch];
            up2(ag[i], lo, hi); float gg = lo + hi + b_ih[ch + 256] + b_hh[ch + 256];
            up2(ao[i], lo, hi); float go = lo + hi + b_ih[ch + 384] + b_hh[ch + 384];
            float cc = sigmoidf_(gi) * tanhf(gg);
            float h  = sigmoidf_(go) * tanhf(cc);
            psum = fmaf(fmaxf(h, 0.f), dec_w[ch], psum);
        }
        sm[PARTS + wid * 32 + lane] = psum;
    }
    __syncthreads();

    if (wid == 0) {
        float acc = dec_b[0];
        #pragma unroll
        for (int w = 0; w < 16; ++w) acc += sm[PARTS + w * 32 + lane];
        out[e0 + lane] = sigmoidf_(acc);
    }
}

extern "C" void kernel_launch(void* const* d_in, const int* in_sizes, int n_in,
                              void* d_out, int out_size)
{
    const float* data   = (const float*)d_in[0];
    // d_in[1] = sr (16000 -> context 64; unused)
    const float* stft_w = (const float*)d_in[2];
    const float* e1_w   = (const float*)d_in[3];
    const float* e1_b   = (const float*)d_in[4];
    const float* e2_w   = (const float*)d_in[5];
    const float* e2_b   = (const float*)d_in[6];
    const float* e3_w   = (const float*)d_in[7];
    const float* e3_b   = (const float*)d_in[8];
    const float* e4_w   = (const float*)d_in[9];
    const float* e4_b   = (const float*)d_in[10];
    const float* w_ih   = (const float*)d_in[11];
    // d_in[12] = w_hh (unused: h0 = 0)
    const float* b_ih   = (const float*)d_in[13];
    const float* b_hh   = (const float*)d_in[14];
    const float* dec_w  = (const float*)d_in[15];
    const float* dec_b  = (const float*)d_in[16];
    float* out = (float*)d_out;

    vad_prep<<<64, 256>>>(stft_w, e1_w, e2_w, e3_w, e4_w);

    int B = in_sizes[0] / 512;
    int grid = B / TB;
    size_t smem = SMEM_FLOATS * sizeof(float);
    cudaFuncSetAttribute(vad_fused, cudaFuncAttributeMaxDynamicSharedMemorySize, (int)smem);
    vad_fused<<<grid, NTHREADS, smem>>>(data,
                                        e1_b, e2_b, e3_b, e4_b,
                                        w_ih, b_ih, b_hh, dec_w, dec_b, out);
}

// round 15
// speedup vs baseline: 1.5199x; 1.5199x over previous
#include <cuda_runtime.h>
#include <math.h>

#define TB 32          // batch elements per CTA (lane == element)
#define NTHREADS 512   // 16 warps

// ---------------- shared memory layout (float offsets) ----------------
// phase A: SIGT  [32768, 53888)   640 x 32, stride 33 (transposed padded signal)
// phase B: SIG2  [0, 32768)       [k=256][e=32][t=4]  (frame-quad layout)
// phase C: MAG   [32768, 49280)   [c=129][e][t=4]     (overwrites dead SIGT)
//          FPART [49280, 53376)   16 warps x 32 e x (4t x re/im)
// phase D: Y1    [0, 16384)       [c=128][e][4]       (overwrites dead SIG2)
//          Y2    [16384, 20480)   [c=64][e][2]
//          Y3    [20480, 22528)   [c=64][e]
//          Y4    [22528, 26624)   [q=32][e][4]  (channel quads)
//          PART  [26624, 27136)
#define SIG2  0
#define SIGT  32768
#define MAG   32768
#define FPART 49280
#define Y1    0
#define Y2    16384
#define Y3    20480
#define Y4    22528
#define PARTS 26624
#define SMEM_FLOATS 53888

// ---------------- packed-weight scratch (__device__ globals, filled by prep) ----
__device__ float g_stft_wp[256 * 264];      // [k][2f interleaved (re,im)], row padded to 264
__device__ float g_e1_wp[32 * 129 * 12];    // [g(4ch)][c][j*4 + ch_in_quad]
__device__ float g_e2_wp[16 * 128 * 12];    // [g][c][j*4 + m]
__device__ float g_e3_wp[16 * 64 * 8];      // [g][c][ch0:(w1,w2), ch1:(w1,w2), ...]
__device__ float g_e4_wp[32 * 64 * 4];      // [g][c][center tap for 4 ch]

typedef unsigned long long f32x2;

static __device__ __forceinline__ f32x2 b2(float v) {
    f32x2 r; unsigned u = __float_as_uint(v);
    asm("mov.b64 %0, {%1,%2};" : "=l"(r) : "r"(u), "r"(u));
    return r;
}
static __device__ __forceinline__ void up2(f32x2 v, float& lo, float& hi) {
    unsigned a, b;
    asm("mov.b64 {%0,%1}, %2;" : "=r"(a), "=r"(b) : "l"(v));
    lo = __uint_as_float(a); hi = __uint_as_float(b);
}
static __device__ __forceinline__ f32x2 ffma2(f32x2 a, f32x2 b, f32x2 c) {
    f32x2 d;
    asm("fma.rn.f32x2 %0, %1, %2, %3;" : "=l"(d) : "l"(a), "l"(b), "l"(c));
    return d;
}
static __device__ __forceinline__ float sigmoidf_(float x) {
    return 1.0f / (1.0f + __expf(-x));
}

// ---------------- weight prep (runs each launch; ~5us) ----------------
__global__ void vad_prep(const float* __restrict__ stft_w,
                         const float* __restrict__ e1_w,
                         const float* __restrict__ e2_w,
                         const float* __restrict__ e3_w,
                         const float* __restrict__ e4_w)
{
    int t0 = blockIdx.x * blockDim.x + threadIdx.x;
    int stride = gridDim.x * blockDim.x;
    for (int i = t0; i < 256 * 129; i += stride) {
        int k = i / 129, f = i - k * 129;
        g_stft_wp[k * 264 + 2 * f]     = stft_w[f * 256 + k];
        g_stft_wp[k * 264 + 2 * f + 1] = stft_w[(f + 129) * 256 + k];
    }
    for (int i = t0; i < 32 * 129 * 12; i += stride) {
        int g = i / (129 * 12), r = i - g * 129 * 12, c = r / 12, jm = r - c * 12;
        int j = jm >> 2, m = jm & 3;
        g_e1_wp[i] = e1_w[(4 * g + m) * 387 + c * 3 + j];
    }
    for (int i = t0; i < 16 * 128 * 12; i += stride) {
        int g = i / (128 * 12), r = i - g * 128 * 12, c = r / 12, jm = r - c * 12;
        int j = jm >> 2, m = jm & 3;
        g_e2_wp[i] = e2_w[(4 * g + m) * 384 + c * 3 + j];
    }
    for (int i = t0; i < 16 * 64 * 8; i += stride) {
        int g = i / (64 * 8), r = i - g * 64 * 8, c = r / 8, m2 = r - c * 8;
        int m = m2 >> 1, j = 1 + (m2 & 1);
        g_e3_wp[i] = e3_w[(4 * g + m) * 192 + c * 3 + j];
    }
    for (int i = t0; i < 32 * 64 * 4; i += stride) {
        int g = i / (64 * 4), r = i - g * 64 * 4, c = r / 4, m = r - c * 4;
        g_e4_wp[i] = e4_w[(4 * g + m) * 192 + c * 3 + 1];
    }
}

// ---------------- main fused kernel ----------------
__global__ void __launch_bounds__(NTHREADS, 1)
vad_fused(const float* __restrict__ data,
          const float* __restrict__ e1_b, const float* __restrict__ e2_b,
          const float* __restrict__ e3_b, const float* __restrict__ e4_b,
          const float* __restrict__ w_ih,
          const float* __restrict__ b_ih, const float* __restrict__ b_hh,
          const float* __restrict__ dec_w, const float* __restrict__ dec_b,
          float* __restrict__ out)
{
    extern __shared__ float sm[];
    const int tid  = threadIdx.x;
    const int wid  = tid >> 5;
    const int lane = tid & 31;
    const long long e0 = (long long)blockIdx.x * TB;
    const float* __restrict__ dbase = data + e0 * 512;

    // -------- phase A: padded signal, transposed (coalesced global reads) --------
    float* sigt = sm + SIGT;  // 640 x 32, stride 33
    for (int idx = tid; idx < 64 * TB; idx += NTHREADS) {
        int p = idx >> 5, e = idx & 31;
        sigt[p * 33 + e] = 0.0f;
    }
    for (int idx = tid; idx < 512 * TB; idx += NTHREADS) {
        int e = idx >> 9, j = idx & 511;
        sigt[(64 + j) * 33 + e] = dbase[idx];
    }
    for (int idx = tid; idx < 64 * TB; idx += NTHREADS) {
        int e = idx >> 6, j = idx & 63;
        sigt[(576 + j) * 33 + e] = dbase[e * 512 + 510 - j];
    }
    __syncthreads();

    // -------- phase B: frame-quad layout sig2[k][e][t] --------
    for (int i = tid; i < 256 * 32; i += NTHREADS) {
        int k = i >> 5, e = i & 31;
        float4 v;
        v.x = sigt[k * 33 + e];
        v.y = sigt[(128 + k) * 33 + e];
        v.z = sigt[(256 + k) * 33 + e];
        v.w = sigt[(384 + k) * 33 + e];
        ((float4*)(sm + SIG2))[k * 32 + e] = v;
    }
    __syncthreads();

    // -------- phase C: STFT + magnitude (f32x2: (re,im) pairs, 8 pairs/warp) --------
    {
        f32x2 acc[8][4];
        #pragma unroll
        for (int f = 0; f < 8; ++f)
            #pragma unroll
            for (int t = 0; t < 4; ++t) acc[f][t] = 0ull;

        const ulonglong2* __restrict__ wps = (const ulonglong2*)g_stft_wp;  // 66 per row
        const float4* __restrict__ s2 = (const float4*)(sm + SIG2);

        #pragma unroll 2
        for (int k = 0; k < 256; ++k) {
            float4 s4 = s2[k * 32 + lane];
            f32x2 S0 = b2(s4.x), S1 = b2(s4.y), S2 = b2(s4.z), S3 = b2(s4.w);
            ulonglong2 w0 = wps[k * 66 + wid * 4 + 0];
            ulonglong2 w1 = wps[k * 66 + wid * 4 + 1];
            ulonglong2 w2 = wps[k * 66 + wid * 4 + 2];
            ulonglong2 w3 = wps[k * 66 + wid * 4 + 3];
            f32x2 W[8] = {w0.x, w0.y, w1.x, w1.y, w2.x, w2.y, w3.x, w3.y};
            #pragma unroll
            for (int f = 0; f < 8; ++f) {
                acc[f][0] = ffma2(W[f], S0, acc[f][0]);
                acc[f][1] = ffma2(W[f], S1, acc[f][1]);
                acc[f][2] = ffma2(W[f], S2, acc[f][2]);
                acc[f][3] = ffma2(W[f], S3, acc[f][3]);
            }
        }
        #pragma unroll
        for (int f = 0; f < 8; ++f) {
            float4 mg;
            #pragma unroll
            for (int t = 0; t < 4; ++t) {
                float re, im; up2(acc[f][t], re, im);
                (&mg.x)[t] = sqrtf(re * re + im * im);
            }
            ((float4*)(sm + MAG))[(8 * wid + f) * 32 + lane] = mg;
        }

        // filter 128: each warp takes a k-slice of 16, partials to smem
        f32x2 r0 = 0ull, r1 = 0ull, r2 = 0ull, r3 = 0ull;
        int kb = wid * 16;
        #pragma unroll
        for (int k = kb; k < kb + 16; ++k) {
            float4 s4 = s2[k * 32 + lane];
            f32x2 W = *(const f32x2*)(g_stft_wp + k * 264 + 256);
            r0 = ffma2(W, b2(s4.x), r0);
            r1 = ffma2(W, b2(s4.y), r1);
            r2 = ffma2(W, b2(s4.z), r2);
            r3 = ffma2(W, b2(s4.w), r3);
        }
        float* fp = sm + FPART + (wid * 32 + lane) * 8;
        float lo, hi;
        up2(r0, lo, hi); fp[0] = lo; fp[1] = hi;
        up2(r1, lo, hi); fp[2] = lo; fp[3] = hi;
        up2(r2, lo, hi); fp[4] = lo; fp[5] = hi;
        up2(r3, lo, hi); fp[6] = lo; fp[7] = hi;
    }
    __syncthreads();
    if (tid < 128) {
        int e = tid & 31, t = tid >> 5;
        float re = 0.f, im = 0.f;
        #pragma unroll
        for (int w = 0; w < 16; ++w) {
            re += sm[FPART + (w * 32 + e) * 8 + 2 * t];
            im += sm[FPART + (w * 32 + e) * 8 + 2 * t + 1];
        }
        sm[MAG + (128 * 32 + e) * 4 + t] = sqrtf(re * re + im * im);
    }
    __syncthreads();

    // -------- e1: conv(129->128, k3, s1, p1), BOTH channel-quads in ONE pass --------
    // Halves the per-warp MAG re-reads vs the two-pass version (identical arithmetic
    // per accumulator, so results are bit-identical).
    {
        const float4* __restrict__ mg = (const float4*)(sm + MAG);
        const int g0 = wid * 2, g1 = wid * 2 + 1;      // two channel quads per warp
        ulonglong2 bb0 = *(const ulonglong2*)(e1_b + 4 * g0);
        ulonglong2 bb1 = *(const ulonglong2*)(e1_b + 4 * g1);
        f32x2 a[4][4];                                  // [chpair][t]
        #pragma unroll
        for (int t = 0; t < 4; ++t) {
            a[0][t] = bb0.x; a[1][t] = bb0.y;
            a[2][t] = bb1.x; a[3][t] = bb1.y;
        }
        const ulonglong2* __restrict__ wq0 = (const ulonglong2*)g_e1_wp + (long)g0 * 129 * 3;
        const ulonglong2* __restrict__ wq1 = (const ulonglong2*)g_e1_wp + (long)g1 * 129 * 3;
        for (int c = 0; c < 129; ++c) {
            float4 m4 = mg[c * 32 + lane];
            f32x2 M0 = b2(m4.x), M1 = b2(m4.y), M2 = b2(m4.z), M3 = b2(m4.w);
            ulonglong2 A0 = wq0[c * 3 + 0];
            ulonglong2 A1 = wq0[c * 3 + 1];
            ulonglong2 A2 = wq0[c * 3 + 2];
            ulonglong2 B0 = wq1[c * 3 + 0];
            ulonglong2 B1 = wq1[c * 3 + 1];
            ulonglong2 B2 = wq1[c * 3 + 2];
            // quad g0, ch-pair 0 (taps A?.x)
            a[0][0] = ffma2(A1.x, M0, ffma2(A2.x, M1, a[0][0]));
            a[0][1] = ffma2(A0.x, M0, ffma2(A1.x, M1, ffma2(A2.x, M2, a[0][1])));
            a[0][2] = ffma2(A0.x, M1, ffma2(A1.x, M2, ffma2(A2.x, M3, a[0][2])));
            a[0][3] = ffma2(A0.x, M2, ffma2(A1.x, M3, a[0][3]));
            // quad g0, ch-pair 1 (taps A?.y)
            a[1][0] = ffma2(A1.y, M0, ffma2(A2.y, M1, a[1][0]));
            a[1][1] = ffma2(A0.y, M0, ffma2(A1.y, M1, ffma2(A2.y, M2, a[1][1])));
            a[1][2] = ffma2(A0.y, M1, ffma2(A1.y, M2, ffma2(A2.y, M3, a[1][2])));
            a[1][3] = ffma2(A0.y, M2, ffma2(A1.y, M3, a[1][3]));
            // quad g1, ch-pair 0 (taps B?.x)
            a[2][0] = ffma2(B1.x, M0, ffma2(B2.x, M1, a[2][0]));
            a[2][1] = ffma2(B0.x, M0, ffma2(B1.x, M1, ffma2(B2.x, M2, a[2][1])));
            a[2][2] = ffma2(B0.x, M1, ffma2(B1.x, M2, ffma2(B2.x, M3, a[2][2])));
            a[2][3] = ffma2(B0.x, M2, ffma2(B1.x, M3, a[2][3]));
            // quad g1, ch-pair 1 (taps B?.y)
            a[3][0] = ffma2(B1.y, M0, ffma2(B2.y, M1, a[3][0]));
            a[3][1] = ffma2(B0.y, M0, ffma2(B1.y, M1, ffma2(B2.y, M2, a[3][1])));
            a[3][2] = ffma2(B0.y, M1, ffma2(B1.y, M2, ffma2(B2.y, M3, a[3][2])));
            a[3][3] = ffma2(B0.y, M2, ffma2(B1.y, M3, a[3][3]));
        }
        #pragma unroll
        for (int cp = 0; cp < 4; ++cp) {
            int g = (cp < 2) ? g0 : g1;
            int chA = 4 * g + 2 * (cp & 1);
            float4 va, vb;
            #pragma unroll
            for (int t = 0; t < 4; ++t) {
                float lo, hi; up2(a[cp][t], lo, hi);
                (&va.x)[t] = fmaxf(lo, 0.f);
                (&vb.x)[t] = fmaxf(hi, 0.f);
            }
            ((float4*)(sm + Y1))[chA * 32 + lane]       = va;
            ((float4*)(sm + Y1))[(chA + 1) * 32 + lane] = vb;
        }
    }
    __syncthreads();

    // -------- e2: conv(128->64, k3, s2, p1), len 4 -> 2 --------
    {
        int g = wid;                                   // channels 4g..4g+3
        ulonglong2 bb = *(const ulonglong2*)(e2_b + 4 * g);
        f32x2 a[2][2];
        a[0][0] = bb.x; a[0][1] = bb.x;
        a[1][0] = bb.y; a[1][1] = bb.y;
        const ulonglong2* __restrict__ wq = (const ulonglong2*)g_e2_wp + (long)g * 128 * 3;
        const float4* __restrict__ y1p = (const float4*)(sm + Y1);
        #pragma unroll 2
        for (int c = 0; c < 128; ++c) {
            float4 v4 = y1p[c * 32 + lane];
            f32x2 V0 = b2(v4.x), V1 = b2(v4.y), V2 = b2(v4.z), V3 = b2(v4.w);
            ulonglong2 W0 = wq[c * 3 + 0];
            ulonglong2 W1 = wq[c * 3 + 1];
            ulonglong2 W2 = wq[c * 3 + 2];
            a[0][0] = ffma2(W1.x, V0, ffma2(W2.x, V1, a[0][0]));
            a[0][1] = ffma2(W0.x, V1, ffma2(W1.x, V2, ffma2(W2.x, V3, a[0][1])));
            a[1][0] = ffma2(W1.y, V0, ffma2(W2.y, V1, a[1][0]));
            a[1][1] = ffma2(W0.y, V1, ffma2(W1.y, V2, ffma2(W2.y, V3, a[1][1])));
        }
        #pragma unroll
        for (int P = 0; P < 2; ++P) {
            int chA = 4 * g + 2 * P;
            float l0, h0, l1, h1;
            up2(a[P][0], l0, h0); up2(a[P][1], l1, h1);
            ((float2*)(sm + Y2))[chA * 32 + lane]       = make_float2(fmaxf(l0, 0.f), fmaxf(l1, 0.f));
            ((float2*)(sm + Y2))[(chA + 1) * 32 + lane] = make_float2(fmaxf(h0, 0.f), fmaxf(h1, 0.f));
        }
    }
    __syncthreads();

    // -------- e3: conv(64->64, k3, s2, p1), len 2 -> 1 (tap-pair packed) --------
    {
        int g = wid;                                   // channels 4g..4g+3
        f32x2 acc[4] = {0ull, 0ull, 0ull, 0ull};
        const ulonglong2* __restrict__ wq = (const ulonglong2*)g_e3_wp + (long)g * 64 * 2;
        #pragma unroll 2
        for (int c = 0; c < 64; ++c) {
            f32x2 v01 = *(const f32x2*)(sm + Y2 + (c * 32 + lane) * 2);
            ulonglong2 L0 = wq[c * 2], L1 = wq[c * 2 + 1];
            acc[0] = ffma2(L0.x, v01, acc[0]);
            acc[1] = ffma2(L0.y, v01, acc[1]);
            acc[2] = ffma2(L1.x, v01, acc[2]);
            acc[3] = ffma2(L1.y, v01, acc[3]);
        }
        #pragma unroll
        for (int m = 0; m < 4; ++m) {
            float lo, hi; up2(acc[m], lo, hi);
            sm[Y3 + (4 * g + m) * 32 + lane] = fmaxf(lo + hi + e3_b[4 * g + m], 0.f);
        }
    }
    __syncthreads();

    // -------- e4: conv(64->128, k3, s1, p1), len 1 (center tap only) --------
    {
        int q0 = wid * 2, q1 = wid * 2 + 1;            // channel quads; 8 channels/warp
        ulonglong2 bA = *(const ulonglong2*)(e4_b + 8 * wid);
        ulonglong2 bB = *(const ulonglong2*)(e4_b + 8 * wid + 4);
        f32x2 aA0 = bA.x, aA1 = bA.y, aB0 = bB.x, aB1 = bB.y;
        const ulonglong2* __restrict__ wq = (const ulonglong2*)g_e4_wp;
        #pragma unroll 2
        for (int c = 0; c < 64; ++c) {
            f32x2 V = b2(sm[Y3 + c * 32 + lane]);
            ulonglong2 WA = wq[q0 * 64 + c];
            ulonglong2 WB = wq[q1 * 64 + c];
            aA0 = ffma2(WA.x, V, aA0); aA1 = ffma2(WA.y, V, aA1);
            aB0 = ffma2(WB.x, V, aB0); aB1 = ffma2(WB.y, V, aB1);
        }
        float l0, h0, l1, h1;
        up2(aA0, l0, h0); up2(aA1, l1, h1);
        ((float4*)(sm + Y4))[q0 * 32 + lane] =
            make_float4(fmaxf(l0, 0.f), fmaxf(h0, 0.f), fmaxf(l1, 0.f), fmaxf(h1, 0.f));
        up2(aB0, l0, h0); up2(aB1, l1, h1);
        ((float4*)(sm + Y4))[q1 * 32 + lane] =
            make_float4(fmaxf(l0, 0.f), fmaxf(h0, 0.f), fmaxf(l1, 0.f), fmaxf(h1, 0.f));
    }
    __syncthreads();

    // -------- LSTM cell (h0=c0=0 => gates i,g,o) + decoder dot (two-pass, low regs) --------
    {
        float psum = 0.f;
        const ulonglong2* __restrict__ W = (const ulonglong2*)w_ih;  // 32 ull2 per row
        const ulonglong2* __restrict__ y4p = (const ulonglong2*)(sm + Y4);
        #pragma unroll
        for (int ib = 0; ib < 2; ++ib) {
            int ch0 = wid * 8 + ib * 4;
            f32x2 ai[4] = {0ull,0ull,0ull,0ull};
            f32x2 ag[4] = {0ull,0ull,0ull,0ull};
            f32x2 ao[4] = {0ull,0ull,0ull,0ull};
            #pragma unroll 2
            for (int c4 = 0; c4 < 32; ++c4) {
                ulonglong2 V = y4p[c4 * 32 + lane];
                #pragma unroll
                for (int i = 0; i < 4; ++i) {
                    int ch = ch0 + i;
                    ulonglong2 wi = W[(ch)       * 32 + c4];
                    ulonglong2 wg = W[(ch + 256) * 32 + c4];
                    ulonglong2 wo = W[(ch + 384) * 32 + c4];
                    ai[i] = ffma2(wi.x, V.x, ai[i]); ai[i] = ffma2(wi.y, V.y, ai[i]);
                    ag[i] = ffma2(wg.x, V.x, ag[i]); ag[i] = ffma2(wg.y, V.y, ag[i]);
                    ao[i] = ffma2(wo.x, V.x, ao[i]); ao[i] = ffma2(wo.y, V.y, ao[i]);
                }
            }
            #pragma unroll
            for (int i = 0; i < 4; ++i) {
                int ch = ch0 + i;
                float lo, hi;
                up2(ai[i], lo, hi); float gi = lo + hi + b_ih[ch]       + b_hh[ch];
                up2(ag[i], lo, hi); float gg = lo + hi + b_ih[ch + 256] + b_hh[ch + 256];
                up2(ao[i], lo, hi); float go = lo + hi + b_ih[ch + 384] + b_hh[ch + 384];
                float cc = sigmoidf_(gi) * tanhf(gg);
                float h  = sigmoidf_(go) * tanhf(cc);
                psum = fmaf(fmaxf(h, 0.f), dec_w[ch], psum);
            }
        }
        sm[PARTS + wid * 32 + lane] = psum;
    }
    __syncthreads();

    if (wid == 0) {
        float acc = dec_b[0];
        #pragma unroll
        for (int w = 0; w < 16; ++w) acc += sm[PARTS + w * 32 + lane];
        out[e0 + lane] = sigmoidf_(acc);
    }
}

extern "C" void kernel_launch(void* const* d_in, const int* in_sizes, int n_in,
                              void* d_out, int out_size)
{
    const float* data   = (const float*)d_in[0];
    // d_in[1] = sr (16000 -> context 64; unused)
    const float* stft_w = (const float*)d_in[2];
    const float* e1_w   = (const float*)d_in[3];
    const float* e1_b   = (const float*)d_in[4];
    const float* e2_w   = (const float*)d_in[5];
    const float* e2_b   = (const float*)d_in[6];
    const float* e3_w   = (const float*)d_in[7];
    const float* e3_b   = (const float*)d_in[8];
    const float* e4_w   = (const float*)d_in[9];
    const float* e4_b   = (const float*)d_in[10];
    const float* w_ih   = (const float*)d_in[11];
    // d_in[12] = w_hh (unused: h0 = 0)
    const float* b_ih   = (const float*)d_in[13];
    const float* b_hh   = (const float*)d_in[14];
    const float* dec_w  = (const float*)d_in[15];
    const float* dec_b  = (const float*)d_in[16];
    float* out = (float*)d_out;

    vad_prep<<<64, 256>>>(stft_w, e1_w, e2_w, e3_w, e4_w);

    int B = in_sizes[0] / 512;
    int grid = B / TB;
    size_t smem = SMEM_FLOATS * sizeof(float);
    cudaFuncSetAttribute(vad_fused, cudaFuncAttributeMaxDynamicSharedMemorySize, (int)smem);
    vad_fused<<<grid, NTHREADS, smem>>>(data,
                                        e1_b, e2_b, e3_b, e4_b,
                                        w_ih, b_ih, b_hh, dec_w, dec_b, out);
}

// round 16
// speedup vs baseline: 1.7913x; 1.1786x over previous
#include <cuda_runtime.h>
#include <math.h>

#define TB 32          // batch elements per CTA (lane == element)
#define NTHREADS 512   // 16 warps

// ---------------- shared memory layout (float offsets) ----------------
// phase A: SIGT  [32768, 53888)   640 x 32, stride 33
// phase B: SIG2  [0, 32768)       [k=256][e=32][t=4] float4
// phase C: MAG   [32768, 49280)   [c=129][e][t=4]   (over dead SIGT)
//          FPART [49280, 53376)
//          WBUF  [53376, 55424)   16 warps x 32 ull2 (STFT weight stage)
// phase D: Y1    [0, 16384)
//          E1BUF [16384, 22528)   16 warps x 96 ull2 (e1 stage; dead SIG2 upper)
//          Y2    [16384, 20480)   (after e1; E1BUF dead)
//          E2BUF [20480, 26624)   16 warps x 96 ull2 (e2 stage)
//          Y3    [20480, 22528)   (after e2)
//          Y4    [22528, 26624)   (after e3)
//          PARTS [26624, 27136)
#define SIG2  0
#define SIGT  32768
#define MAG   32768
#define FPART 49280
#define WBUF  53376
#define Y1    0
#define E1BUF 16384
#define Y2    16384
#define E2BUF 20480
#define Y3    20480
#define Y4    22528
#define PARTS 26624
#define SMEM_FLOATS 55424   // 221,696 B

// ---------------- packed-weight scratch (__device__ globals, filled by prep) ----
__device__ __align__(16) float g_stft_wp2[16 * 256 * 16]; // [p=warp][k][4 ull2: pairs 8p..8p+7 (re,im)]
__device__ __align__(16) float g_stft_w128[512];          // [k][re,im] for filter 128
__device__ __align__(16) float g_e1_wp[16 * 129 * 24];    // [p][c][6 ull2: quad 2p taps0-2, quad 2p+1 taps0-2]
__device__ __align__(16) float g_e2_wp[16 * 128 * 12];    // [g][c][3 ull2]
__device__ __align__(16) float g_e3_wp[16 * 64 * 8];      // [g][c][2 ull2]
__device__ __align__(16) float g_e4_wp[32 * 64 * 4];      // [q][c][1 ull2]
__device__ __align__(16) float g_lstm_wp[16 * 32 * 96];   // [p][c4][24 ull2: i-gate ch0-7, g-gate, o-gate]

typedef unsigned long long f32x2;

static __device__ __forceinline__ f32x2 b2(float v) {
    f32x2 r; unsigned u = __float_as_uint(v);
    asm("mov.b64 %0, {%1,%2};" : "=l"(r) : "r"(u), "r"(u));
    return r;
}
static __device__ __forceinline__ void up2(f32x2 v, float& lo, float& hi) {
    unsigned a, b;
    asm("mov.b64 {%0,%1}, %2;" : "=r"(a), "=r"(b) : "l"(v));
    lo = __uint_as_float(a); hi = __uint_as_float(b);
}
static __device__ __forceinline__ f32x2 ffma2(f32x2 a, f32x2 b, f32x2 c) {
    f32x2 d;
    asm("fma.rn.f32x2 %0, %1, %2, %3;" : "=l"(d) : "l"(a), "l"(b), "l"(c));
    return d;
}
static __device__ __forceinline__ float sigmoidf_(float x) {
    return 1.0f / (1.0f + __expf(-x));
}

// ---------------- weight prep (runs each launch; ~10us) ----------------
__global__ void vad_prep(const float* __restrict__ stft_w,
                         const float* __restrict__ e1_w,
                         const float* __restrict__ e2_w,
                         const float* __restrict__ e3_w,
                         const float* __restrict__ e4_w,
                         const float* __restrict__ w_ih)
{
    int t0 = blockIdx.x * blockDim.x + threadIdx.x;
    int stride = gridDim.x * blockDim.x;
    // STFT: [p][k][16 floats]: q=jj*4+u -> pair f = 8p+2jj+(u>>1); u&1 selects imag
    for (int i = t0; i < 16 * 256 * 16; i += stride) {
        int p = i >> 12, r = i & 4095, k = r >> 4, q = r & 15;
        int jj = q >> 2, u = q & 3;
        int f = 8 * p + 2 * jj + (u >> 1);
        int row = (u & 1) ? f + 129 : f;
        g_stft_wp2[i] = stft_w[row * 256 + k];
    }
    for (int i = t0; i < 512; i += stride) {
        int k = i >> 1;
        g_stft_w128[i] = stft_w[((i & 1) ? 257 : 128) * 256 + k];
    }
    // e1: [p][c][24 floats]: j = ull2 idx (0..5), m = channel in quad
    for (int i = t0; i < 16 * 129 * 24; i += stride) {
        int p = i / (129 * 24), r = i % (129 * 24), c = r / 24, q = r % 24;
        int j = q >> 2, m = q & 3;
        int g = 2 * p + (j >= 3 ? 1 : 0);
        int tap = j % 3;
        g_e1_wp[i] = e1_w[(4 * g + m) * 387 + c * 3 + tap];
    }
    for (int i = t0; i < 16 * 128 * 12; i += stride) {
        int g = i / (128 * 12), r = i - g * 128 * 12, c = r / 12, jm = r - c * 12;
        int j = jm >> 2, m = jm & 3;
        g_e2_wp[i] = e2_w[(4 * g + m) * 384 + c * 3 + j];
    }
    for (int i = t0; i < 16 * 64 * 8; i += stride) {
        int g = i / (64 * 8), r = i - g * 64 * 8, c = r / 8, m2 = r - c * 8;
        int m = m2 >> 1, j = 1 + (m2 & 1);
        g_e3_wp[i] = e3_w[(4 * g + m) * 192 + c * 3 + j];
    }
    for (int i = t0; i < 32 * 64 * 4; i += stride) {
        int g = i / (64 * 4), r = i - g * 64 * 4, c = r / 4, m = r - c * 4;
        g_e4_wp[i] = e4_w[(4 * g + m) * 192 + c * 3 + 1];
    }
    // LSTM: [p][c4][96 floats]: rr = gate*8 + i, u = elem in c4
    for (int i = t0; i < 16 * 32 * 96; i += stride) {
        int p = i / 3072, r = i % 3072, c4 = r / 96, q = r % 96;
        int rr = q >> 2, u = q & 3;
        int gate = rr >> 3, ii = rr & 7;
        int row = p * 8 + ii + (gate == 0 ? 0 : (gate == 1 ? 256 : 384));
        g_lstm_wp[i] = w_ih[row * 128 + c4 * 4 + u];
    }
}

// ---------------- main fused kernel ----------------
__global__ void __launch_bounds__(NTHREADS, 1)
vad_fused(const float* __restrict__ data,
          const float* __restrict__ e1_b, const float* __restrict__ e2_b,
          const float* __restrict__ e3_b, const float* __restrict__ e4_b,
          const float* __restrict__ b_ih, const float* __restrict__ b_hh,
          const float* __restrict__ dec_w, const float* __restrict__ dec_b,
          float* __restrict__ out)
{
    extern __shared__ float sm[];
    const int tid  = threadIdx.x;
    const int wid  = tid >> 5;
    const int lane = tid & 31;
    const long long e0 = (long long)blockIdx.x * TB;
    const float* __restrict__ dbase = data + e0 * 512;

    // -------- phase A: padded signal, transposed (coalesced global reads) --------
    float* sigt = sm + SIGT;  // 640 x 32, stride 33
    for (int idx = tid; idx < 64 * TB; idx += NTHREADS) {
        int p = idx >> 5, e = idx & 31;
        sigt[p * 33 + e] = 0.0f;
    }
    for (int idx = tid; idx < 512 * TB; idx += NTHREADS) {
        int e = idx >> 9, j = idx & 511;
        sigt[(64 + j) * 33 + e] = dbase[idx];
    }
    for (int idx = tid; idx < 64 * TB; idx += NTHREADS) {
        int e = idx >> 6, j = idx & 63;
        sigt[(576 + j) * 33 + e] = dbase[e * 512 + 510 - j];
    }
    __syncthreads();

    // -------- phase B: frame-quad layout sig2[k][e][t] --------
    for (int i = tid; i < 256 * 32; i += NTHREADS) {
        int k = i >> 5, e = i & 31;
        float4 v;
        v.x = sigt[k * 33 + e];
        v.y = sigt[(128 + k) * 33 + e];
        v.z = sigt[(256 + k) * 33 + e];
        v.w = sigt[(384 + k) * 33 + e];
        ((float4*)(sm + SIG2))[k * 32 + e] = v;
    }
    __syncthreads();

    // -------- phase C: STFT + magnitude, staged weights (8 k per tile) --------
    {
        f32x2 acc[8][4];
        #pragma unroll
        for (int f = 0; f < 8; ++f)
            #pragma unroll
            for (int t = 0; t < 4; ++t) acc[f][t] = 0ull;

        const float4* __restrict__ s2 = (const float4*)(sm + SIG2);
        const ulonglong2* __restrict__ wsl = (const ulonglong2*)g_stft_wp2 + (size_t)wid * 1024;
        ulonglong2* wb = (ulonglong2*)(sm + WBUF) + wid * 32;

        ulonglong2 pf = wsl[lane];          // tile 0
        wb[lane] = pf;
        __syncwarp();

        for (int T = 0; T < 32; ++T) {
            if (T < 31) pf = wsl[(T + 1) * 32 + lane];   // prefetch next tile
            #pragma unroll
            for (int kk = 0; kk < 8; ++kk) {
                int k = T * 8 + kk;
                float4 s4 = s2[k * 32 + lane];
                f32x2 S0 = b2(s4.x), S1 = b2(s4.y), S2 = b2(s4.z), S3 = b2(s4.w);
                ulonglong2 q0 = wb[kk * 4 + 0];
                ulonglong2 q1 = wb[kk * 4 + 1];
                ulonglong2 q2 = wb[kk * 4 + 2];
                ulonglong2 q3 = wb[kk * 4 + 3];
                f32x2 W[8] = {q0.x, q0.y, q1.x, q1.y, q2.x, q2.y, q3.x, q3.y};
                #pragma unroll
                for (int f = 0; f < 8; ++f) {
                    acc[f][0] = ffma2(W[f], S0, acc[f][0]);
                    acc[f][1] = ffma2(W[f], S1, acc[f][1]);
                    acc[f][2] = ffma2(W[f], S2, acc[f][2]);
                    acc[f][3] = ffma2(W[f], S3, acc[f][3]);
                }
            }
            if (T < 31) { __syncwarp(); wb[lane] = pf; __syncwarp(); }
        }
        #pragma unroll
        for (int f = 0; f < 8; ++f) {
            float4 mg;
            #pragma unroll
            for (int t = 0; t < 4; ++t) {
                float re, im; up2(acc[f][t], re, im);
                (&mg.x)[t] = sqrtf(re * re + im * im);
            }
            ((float4*)(sm + MAG))[(8 * wid + f) * 32 + lane] = mg;
        }

        // filter 128: each warp takes a k-slice of 16, partials to smem
        f32x2 r0 = 0ull, r1 = 0ull, r2 = 0ull, r3 = 0ull;
        int kb = wid * 16;
        #pragma unroll
        for (int k = kb; k < kb + 16; ++k) {
            float4 s4 = s2[k * 32 + lane];
            f32x2 W = *(const f32x2*)(g_stft_w128 + k * 2);
            r0 = ffma2(W, b2(s4.x), r0);
            r1 = ffma2(W, b2(s4.y), r1);
            r2 = ffma2(W, b2(s4.z), r2);
            r3 = ffma2(W, b2(s4.w), r3);
        }
        float* fp = sm + FPART + (wid * 32 + lane) * 8;
        float lo, hi;
        up2(r0, lo, hi); fp[0] = lo; fp[1] = hi;
        up2(r1, lo, hi); fp[2] = lo; fp[3] = hi;
        up2(r2, lo, hi); fp[4] = lo; fp[5] = hi;
        up2(r3, lo, hi); fp[6] = lo; fp[7] = hi;
    }
    __syncthreads();
    if (tid < 128) {
        int e = tid & 31, t = tid >> 5;
        float re = 0.f, im = 0.f;
        #pragma unroll
        for (int w = 0; w < 16; ++w) {
            re += sm[FPART + (w * 32 + e) * 8 + 2 * t];
            im += sm[FPART + (w * 32 + e) * 8 + 2 * t + 1];
        }
        sm[MAG + (128 * 32 + e) * 4 + t] = sqrtf(re * re + im * im);
    }
    __syncthreads();

    // -------- e1: conv(129->128), staged weights (16 c per tile), single pass --------
    {
        const float4* __restrict__ mg = (const float4*)(sm + MAG);
        const ulonglong2* __restrict__ wsl = (const ulonglong2*)g_e1_wp + (size_t)wid * 774; // 129*6
        ulonglong2* eb = (ulonglong2*)(sm + E1BUF) + wid * 96;

        ulonglong2 bb0 = *(const ulonglong2*)(e1_b + 8 * wid);
        ulonglong2 bb1 = *(const ulonglong2*)(e1_b + 8 * wid + 4);
        f32x2 a[4][4];
        #pragma unroll
        for (int t = 0; t < 4; ++t) {
            a[0][t] = bb0.x; a[1][t] = bb0.y;
            a[2][t] = bb1.x; a[3][t] = bb1.y;
        }

        ulonglong2 pf0 = wsl[lane], pf1 = wsl[lane + 32], pf2 = wsl[lane + 64];
        eb[lane] = pf0; eb[lane + 32] = pf1; eb[lane + 64] = pf2;
        __syncwarp();

        for (int T = 0; T < 8; ++T) {
            if (T < 7) {
                int b = (T + 1) * 96;
                pf0 = wsl[b + lane]; pf1 = wsl[b + lane + 32]; pf2 = wsl[b + lane + 64];
            }
            #pragma unroll 2
            for (int cc = 0; cc < 16; ++cc) {
                int c = T * 16 + cc;
                float4 m4 = mg[c * 32 + lane];
                f32x2 M0 = b2(m4.x), M1 = b2(m4.y), M2 = b2(m4.z), M3 = b2(m4.w);
                ulonglong2 A0 = eb[cc * 6 + 0];
                ulonglong2 A1 = eb[cc * 6 + 1];
                ulonglong2 A2 = eb[cc * 6 + 2];
                ulonglong2 B0 = eb[cc * 6 + 3];
                ulonglong2 B1 = eb[cc * 6 + 4];
                ulonglong2 B2 = eb[cc * 6 + 5];
                a[0][0] = ffma2(A1.x, M0, ffma2(A2.x, M1, a[0][0]));
                a[0][1] = ffma2(A0.x, M0, ffma2(A1.x, M1, ffma2(A2.x, M2, a[0][1])));
                a[0][2] = ffma2(A0.x, M1, ffma2(A1.x, M2, ffma2(A2.x, M3, a[0][2])));
                a[0][3] = ffma2(A0.x, M2, ffma2(A1.x, M3, a[0][3]));
                a[1][0] = ffma2(A1.y, M0, ffma2(A2.y, M1, a[1][0]));
                a[1][1] = ffma2(A0.y, M0, ffma2(A1.y, M1, ffma2(A2.y, M2, a[1][1])));
                a[1][2] = ffma2(A0.y, M1, ffma2(A1.y, M2, ffma2(A2.y, M3, a[1][2])));
                a[1][3] = ffma2(A0.y, M2, ffma2(A1.y, M3, a[1][3]));
                a[2][0] = ffma2(B1.x, M0, ffma2(B2.x, M1, a[2][0]));
                a[2][1] = ffma2(B0.x, M0, ffma2(B1.x, M1, ffma2(B2.x, M2, a[2][1])));
                a[2][2] = ffma2(B0.x, M1, ffma2(B1.x, M2, ffma2(B2.x, M3, a[2][2])));
                a[2][3] = ffma2(B0.x, M2, ffma2(B1.x, M3, a[2][3]));
                a[3][0] = ffma2(B1.y, M0, ffma2(B2.y, M1, a[3][0]));
                a[3][1] = ffma2(B0.y, M0, ffma2(B1.y, M1, ffma2(B2.y, M2, a[3][1])));
                a[3][2] = ffma2(B0.y, M1, ffma2(B1.y, M2, ffma2(B2.y, M3, a[3][2])));
                a[3][3] = ffma2(B0.y, M2, ffma2(B1.y, M3, a[3][3]));
            }
            if (T < 7) {
                __syncwarp();
                eb[lane] = pf0; eb[lane + 32] = pf1; eb[lane + 64] = pf2;
                __syncwarp();
            }
        }
        // c = 128 tail (direct loads)
        {
            float4 m4 = mg[128 * 32 + lane];
            f32x2 M0 = b2(m4.x), M1 = b2(m4.y), M2 = b2(m4.z), M3 = b2(m4.w);
            const ulonglong2* tb = wsl + 768;
            ulonglong2 A0 = tb[0], A1 = tb[1], A2 = tb[2], B0 = tb[3], B1 = tb[4], B2 = tb[5];
            a[0][0] = ffma2(A1.x, M0, ffma2(A2.x, M1, a[0][0]));
            a[0][1] = ffma2(A0.x, M0, ffma2(A1.x, M1, ffma2(A2.x, M2, a[0][1])));
            a[0][2] = ffma2(A0.x, M1, ffma2(A1.x, M2, ffma2(A2.x, M3, a[0][2])));
            a[0][3] = ffma2(A0.x, M2, ffma2(A1.x, M3, a[0][3]));
            a[1][0] = ffma2(A1.y, M0, ffma2(A2.y, M1, a[1][0]));
            a[1][1] = ffma2(A0.y, M0, ffma2(A1.y, M1, ffma2(A2.y, M2, a[1][1])));
            a[1][2] = ffma2(A0.y, M1, ffma2(A1.y, M2, ffma2(A2.y, M3, a[1][2])));
            a[1][3] = ffma2(A0.y, M2, ffma2(A1.y, M3, a[1][3]));
            a[2][0] = ffma2(B1.x, M0, ffma2(B2.x, M1, a[2][0]));
            a[2][1] = ffma2(B0.x, M0, ffma2(B1.x, M1, ffma2(B2.x, M2, a[2][1])));
            a[2][2] = ffma2(B0.x, M1, ffma2(B1.x, M2, ffma2(B2.x, M3, a[2][2])));
            a[2][3] = ffma2(B0.x, M2, ffma2(B1.x, M3, a[2][3]));
            a[3][0] = ffma2(B1.y, M0, ffma2(B2.y, M1, a[3][0]));
            a[3][1] = ffma2(B0.y, M0, ffma2(B1.y, M1, ffma2(B2.y, M2, a[3][1])));
            a[3][2] = ffma2(B0.y, M1, ffma2(B1.y, M2, ffma2(B2.y, M3, a[3][2])));
            a[3][3] = ffma2(B0.y, M2, ffma2(B1.y, M3, a[3][3]));
        }
        #pragma unroll
        for (int cp = 0; cp < 4; ++cp) {
            int g = wid * 2 + (cp >> 1);
            int chA = 4 * g + 2 * (cp & 1);
            float4 va, vb;
            #pragma unroll
            for (int t = 0; t < 4; ++t) {
                float lo, hi; up2(a[cp][t], lo, hi);
                (&va.x)[t] = fmaxf(lo, 0.f);
                (&vb.x)[t] = fmaxf(hi, 0.f);
            }
            ((float4*)(sm + Y1))[chA * 32 + lane]       = va;
            ((float4*)(sm + Y1))[(chA + 1) * 32 + lane] = vb;
        }
    }
    __syncthreads();

    // -------- e2: conv(128->64), staged weights (32 c per tile) --------
    {
        int g = wid;
        ulonglong2 bb = *(const ulonglong2*)(e2_b + 4 * g);
        f32x2 a[2][2];
        a[0][0] = bb.x; a[0][1] = bb.x;
        a[1][0] = bb.y; a[1][1] = bb.y;
        const ulonglong2* __restrict__ wq = (const ulonglong2*)g_e2_wp + (size_t)g * 384;
        const float4* __restrict__ y1p = (const float4*)(sm + Y1);
        ulonglong2* eb = (ulonglong2*)(sm + E2BUF) + wid * 96;

        ulonglong2 pf0 = wq[lane], pf1 = wq[lane + 32], pf2 = wq[lane + 64];
        eb[lane] = pf0; eb[lane + 32] = pf1; eb[lane + 64] = pf2;
        __syncwarp();

        for (int T = 0; T < 4; ++T) {
            if (T < 3) {
                int b = (T + 1) * 96;
                pf0 = wq[b + lane]; pf1 = wq[b + lane + 32]; pf2 = wq[b + lane + 64];
            }
            #pragma unroll 2
            for (int cc = 0; cc < 32; ++cc) {
                int c = T * 32 + cc;
                float4 v4 = y1p[c * 32 + lane];
                f32x2 V0 = b2(v4.x), V1 = b2(v4.y), V2 = b2(v4.z), V3 = b2(v4.w);
                ulonglong2 W0 = eb[cc * 3 + 0];
                ulonglong2 W1 = eb[cc * 3 + 1];
                ulonglong2 W2 = eb[cc * 3 + 2];
                a[0][0] = ffma2(W1.x, V0, ffma2(W2.x, V1, a[0][0]));
                a[0][1] = ffma2(W0.x, V1, ffma2(W1.x, V2, ffma2(W2.x, V3, a[0][1])));
                a[1][0] = ffma2(W1.y, V0, ffma2(W2.y, V1, a[1][0]));
                a[1][1] = ffma2(W0.y, V1, ffma2(W1.y, V2, ffma2(W2.y, V3, a[1][1])));
            }
            if (T < 3) {
                __syncwarp();
                eb[lane] = pf0; eb[lane + 32] = pf1; eb[lane + 64] = pf2;
                __syncwarp();
            }
        }
        #pragma unroll
        for (int P = 0; P < 2; ++P) {
            int chA = 4 * g + 2 * P;
            float l0, h0, l1, h1;
            up2(a[P][0], l0, h0); up2(a[P][1], l1, h1);
            ((float2*)(sm + Y2))[chA * 32 + lane]       = make_float2(fmaxf(l0, 0.f), fmaxf(l1, 0.f));
            ((float2*)(sm + Y2))[(chA + 1) * 32 + lane] = make_float2(fmaxf(h0, 0.f), fmaxf(h1, 0.f));
        }
    }
    __syncthreads();

    // -------- e3: conv(64->64, k3, s2, p1), len 2 -> 1 (tap-pair packed) --------
    {
        int g = wid;
        f32x2 acc[4] = {0ull, 0ull, 0ull, 0ull};
        const ulonglong2* __restrict__ wq = (const ulonglong2*)g_e3_wp + (size_t)g * 128;
        #pragma unroll 2
        for (int c = 0; c < 64; ++c) {
            f32x2 v01 = *(const f32x2*)(sm + Y2 + (c * 32 + lane) * 2);
            ulonglong2 L0 = wq[c * 2], L1 = wq[c * 2 + 1];
            acc[0] = ffma2(L0.x, v01, acc[0]);
            acc[1] = ffma2(L0.y, v01, acc[1]);
            acc[2] = ffma2(L1.x, v01, acc[2]);
            acc[3] = ffma2(L1.y, v01, acc[3]);
        }
        #pragma unroll
        for (int m = 0; m < 4; ++m) {
            float lo, hi; up2(acc[m], lo, hi);
            sm[Y3 + (4 * g + m) * 32 + lane] = fmaxf(lo + hi + e3_b[4 * g + m], 0.f);
        }
    }
    __syncthreads();

    // -------- e4: conv(64->128), len 1 (center tap only) --------
    {
        int q0 = wid * 2, q1 = wid * 2 + 1;
        ulonglong2 bA = *(const ulonglong2*)(e4_b + 8 * wid);
        ulonglong2 bB = *(const ulonglong2*)(e4_b + 8 * wid + 4);
        f32x2 aA0 = bA.x, aA1 = bA.y, aB0 = bB.x, aB1 = bB.y;
        const ulonglong2* __restrict__ wq = (const ulonglong2*)g_e4_wp;
        #pragma unroll 2
        for (int c = 0; c < 64; ++c) {
            f32x2 V = b2(sm[Y3 + c * 32 + lane]);
            ulonglong2 WA = wq[q0 * 64 + c];
            ulonglong2 WB = wq[q1 * 64 + c];
            aA0 = ffma2(WA.x, V, aA0); aA1 = ffma2(WA.y, V, aA1);
            aB0 = ffma2(WB.x, V, aB0); aB1 = ffma2(WB.y, V, aB1);
        }
        float l0, h0, l1, h1;
        up2(aA0, l0, h0); up2(aA1, l1, h1);
        ((float4*)(sm + Y4))[q0 * 32 + lane] =
            make_float4(fmaxf(l0, 0.f), fmaxf(h0, 0.f), fmaxf(l1, 0.f), fmaxf(h1, 0.f));
        up2(aB0, l0, h0); up2(aB1, l1, h1);
        ((float4*)(sm + Y4))[q1 * 32 + lane] =
            make_float4(fmaxf(l0, 0.f), fmaxf(h0, 0.f), fmaxf(l1, 0.f), fmaxf(h1, 0.f));
    }
    __syncthreads();

    // -------- LSTM (h0=c0=0 => gates i,g,o), repacked contiguous weights --------
    {
        float psum = 0.f;
        const ulonglong2* __restrict__ wl = (const ulonglong2*)g_lstm_wp + (size_t)wid * 768;
        const ulonglong2* __restrict__ y4p = (const ulonglong2*)(sm + Y4);
        #pragma unroll
        for (int ib = 0; ib < 2; ++ib) {
            f32x2 ai[4] = {0ull,0ull,0ull,0ull};
            f32x2 ag[4] = {0ull,0ull,0ull,0ull};
            f32x2 ao[4] = {0ull,0ull,0ull,0ull};
            #pragma unroll 2
            for (int c4 = 0; c4 < 32; ++c4) {
                ulonglong2 V = y4p[c4 * 32 + lane];
                #pragma unroll
                for (int i = 0; i < 4; ++i) {
                    ulonglong2 wi = wl[c4 * 24 + ib * 4 + i];
                    ulonglong2 wg = wl[c4 * 24 + 8 + ib * 4 + i];
                    ulonglong2 wo = wl[c4 * 24 + 16 + ib * 4 + i];
                    ai[i] = ffma2(wi.x, V.x, ai[i]); ai[i] = ffma2(wi.y, V.y, ai[i]);
                    ag[i] = ffma2(wg.x, V.x, ag[i]); ag[i] = ffma2(wg.y, V.y, ag[i]);
                    ao[i] = ffma2(wo.x, V.x, ao[i]); ao[i] = ffma2(wo.y, V.y, ao[i]);
                }
            }
            #pragma unroll
            for (int i = 0; i < 4; ++i) {
                int ch = wid * 8 + ib * 4 + i;
                float lo, hi;
                up2(ai[i], lo, hi); float gi = lo + hi + b_ih[ch]       + b_hh[ch];
                up2(ag[i], lo, hi); float gg = lo + hi + b_ih[ch + 256] + b_hh[ch + 256];
                up2(ao[i], lo, hi); float go = lo + hi + b_ih[ch + 384] + b_hh[ch + 384];
                float cc = sigmoidf_(gi) * tanhf(gg);
                float h  = sigmoidf_(go) * tanhf(cc);
                psum = fmaf(fmaxf(h, 0.f), dec_w[ch], psum);
            }
        }
        sm[PARTS + wid * 32 + lane] = psum;
    }
    __syncthreads();

    if (wid == 0) {
        float acc = dec_b[0];
        #pragma unroll
        for (int w = 0; w < 16; ++w) acc += sm[PARTS + w * 32 + lane];
        out[e0 + lane] = sigmoidf_(acc);
    }
}

extern "C" void kernel_launch(void* const* d_in, const int* in_sizes, int n_in,
                              void* d_out, int out_size)
{
    const float* data   = (const float*)d_in[0];
    // d_in[1] = sr (16000 -> context 64; unused)
    const float* stft_w = (const float*)d_in[2];
    const float* e1_w   = (const float*)d_in[3];
    const float* e1_b   = (const float*)d_in[4];
    const float* e2_w   = (const float*)d_in[5];
    const float* e2_b   = (const float*)d_in[6];
    const float* e3_w   = (const float*)d_in[7];
    const float* e3_b   = (const float*)d_in[8];
    const float* e4_w   = (const float*)d_in[9];
    const float* e4_b   = (const float*)d_in[10];
    const float* w_ih   = (const float*)d_in[11];
    // d_in[12] = w_hh (unused: h0 = 0)
    const float* b_ih   = (const float*)d_in[13];
    const float* b_hh   = (const float*)d_in[14];
    const float* dec_w  = (const float*)d_in[15];
    const float* dec_b  = (const float*)d_in[16];
    float* out = (float*)d_out;

    vad_prep<<<64, 256>>>(stft_w, e1_w, e2_w, e3_w, e4_w, w_ih);

    int B = in_sizes[0] / 512;
    int grid = B / TB;
    size_t smem = SMEM_FLOATS * sizeof(float);
    cudaFuncSetAttribute(vad_fused, cudaFuncAttributeMaxDynamicSharedMemorySize, (int)smem);
    vad_fused<<<grid, NTHREADS, smem>>>(data,
                                        e1_b, e2_b, e3_b, e4_b,
                                        b_ih, b_hh, dec_w, dec_b, out);
}